// round 1
// baseline (speedup 1.0000x reference)
#include <cuda_runtime.h>
#include <math.h>

#define N_ROWS  8192
#define N_PROP  2000
#define THREADS 256

// penalty_window argmax per row, then gather.
// Layout contract (metadata order): d_in[0]=rois (N,4), d_in[1]=rpn_rois (N,NP,5),
// d_in[2]=scores (N,NP,2). d_out = [sel_rpn_rois (N,4) | sel_scores (N,1)] flattened.
__global__ __launch_bounds__(THREADS)
void trnms_kernel(const float* __restrict__ rois,
                  const float* __restrict__ rpn,
                  const float* __restrict__ scores,
                  float* __restrict__ out)
{
    const int row = blockIdx.x;
    const int tid = threadIdx.x;

    // ---- per-row reference stats (exact fp32 op order of _rois_vals) ----
    const float4 rr = *reinterpret_cast<const float4*>(rois + (size_t)row * 4);
    const float x = __fmul_rn(__fadd_rn(rr.x, rr.z), 0.5f);
    const float y = __fmul_rn(__fadd_rn(rr.y, rr.w), 0.5f);
    const float w = __fadd_rn(fabsf(__fadd_rn(rr.x, -rr.z)), 1e-4f);
    const float h = __fadd_rn(fabsf(__fadd_rn(rr.y, -rr.w)), 1e-4f);
    const float p = __fmul_rn(__fadd_rn(w, h), 0.5f);
    const float s = sqrtf(__fmul_rn(__fadd_rn(w, p), __fadd_rn(h, p)));
    const float ratio  = __fdiv_rn(w, h);
    const float r_max  = fmaxf(ratio, __fdiv_rn(1.0f, ratio));
    const float window = __fmul_rn(s, 2.0f);
    const float PI_F   = 3.14159274101257324219f;  // fp32(3.141592653589793)

    float best = -INFINITY;
    int   bidx = 0x7fffffff;

    const float* rbase = rpn    + (long long)row * (N_PROP * 5);
    const float* sbase = scores + (long long)row * (N_PROP * 2);

    for (int j = tid; j < N_PROP; j += THREADS) {
        const float* q = rbase + j * 5;
        const float a0 = __ldg(q + 1);
        const float a1 = __ldg(q + 2);
        const float a2 = __ldg(q + 3);
        const float a3 = __ldg(q + 4);
        const float sc = __ldg(sbase + j * 2 + 1);

        // proposal stats
        const float x_ = __fmul_rn(__fadd_rn(a0, a2), 0.5f);
        const float y_ = __fmul_rn(__fadd_rn(a1, a3), 0.5f);
        const float w_ = __fadd_rn(fabsf(__fadd_rn(a0, -a2)), 1e-4f);
        const float h_ = __fadd_rn(fabsf(__fadd_rn(a1, -a3)), 1e-4f);
        const float p_ = __fmul_rn(__fadd_rn(w_, h_), 0.5f);
        const float s_ = sqrtf(__fmul_rn(__fadd_rn(w_, p_), __fadd_rn(h_, p_)));

        // penalty
        const float smax = fmaxf(__fdiv_rn(s, s_), __fdiv_rn(s_, s));
        const float pen  = expf(__fmul_rn(-0.055f,
                              __fadd_rn(__fmul_rn(smax, r_max), -1.0f)));

        // hanning window
        const float dx   = __fadd_rn(x, -x_);
        const float dy   = __fadd_rn(y, -y_);
        const float dist = sqrtf(__fadd_rn(__fmul_rn(dx, dx), __fmul_rn(dy, dy)));
        float han = __fadd_rn(0.5f, __fmul_rn(0.5f,
                        cosf(__fdiv_rn(__fmul_rn(dist, PI_F), window))));
        han = (dist > window) ? 0.0f : han;

        const float pw = __fadd_rn(__fmul_rn(sc, pen), __fmul_rn(han, 0.42f));
        // strict > keeps the lowest j for this thread (matches jnp.argmax first-hit)
        if (pw > best) { best = pw; bidx = j; }
    }

    // ---- block argmax reduction, first-index wins on ties ----
    const int lane = tid & 31;
    const int wid  = tid >> 5;

    #pragma unroll
    for (int off = 16; off > 0; off >>= 1) {
        const float ov = __shfl_down_sync(0xffffffffu, best, off);
        const int   oi = __shfl_down_sync(0xffffffffu, bidx, off);
        if (ov > best || (ov == best && oi < bidx)) { best = ov; bidx = oi; }
    }

    __shared__ float sv[THREADS / 32];
    __shared__ int   si[THREADS / 32];
    if (lane == 0) { sv[wid] = best; si[wid] = bidx; }
    __syncthreads();

    if (wid == 0) {
        best = (lane < THREADS / 32) ? sv[lane] : -INFINITY;
        bidx = (lane < THREADS / 32) ? si[lane] : 0x7fffffff;
        #pragma unroll
        for (int off = (THREADS / 32) / 2; off > 0; off >>= 1) {
            const float ov = __shfl_down_sync(0xffffffffu, best, off);
            const int   oi = __shfl_down_sync(0xffffffffu, bidx, off);
            if (ov > best || (ov == best && oi < bidx)) { best = ov; bidx = oi; }
        }
        if (lane == 0) {
            const float* q = rbase + (long long)bidx * 5;
            float* o = out + (size_t)row * 4;
            o[0] = q[1];
            o[1] = q[2];
            o[2] = q[3];
            o[3] = q[4];
            out[(size_t)N_ROWS * 4 + row] = sbase[bidx * 2 + 1];
        }
    }
}

extern "C" void kernel_launch(void* const* d_in, const int* in_sizes, int n_in,
                              void* d_out, int out_size)
{
    const float* rois   = (const float*)d_in[0];
    const float* rpn    = (const float*)d_in[1];
    const float* scores = (const float*)d_in[2];
    float* out = (float*)d_out;

    trnms_kernel<<<N_ROWS, THREADS>>>(rois, rpn, scores, out);
}